// round 16
// baseline (speedup 1.0000x reference)
#include <cuda_runtime.h>
#include <cuda_bf16.h>
#include <math.h>

#define BATCH 8192
#define DIM 16
#define DIM1 48
#define VOCAB 32000
#define TTH 20
#define FULLM 0xffffffffu

// Split-bf16 operands for the tensor-core logits GEMM (static scratch).
// Layout: [row][16] bf16 == 8 uint32 k-pairs per row (k-pair i = {2i, 2i+1}).
__device__ unsigned g_ohi[BATCH * 8];
__device__ unsigned g_olo[BATCH * 8];
__device__ unsigned g_ehi[VOCAB * 8];
__device__ unsigned g_elo[VOCAB * 8];

// ---------------------------------------------------------------------------
// Kernel E: split E fp32 -> (e_hi, e_lo) bf16 pairs.  x = hi + lo + O(2^-18 x)
// ---------------------------------------------------------------------------
__global__ void __launch_bounds__(256) convertE_kernel(const float* __restrict__ E) {
    int i = blockIdx.x * 256 + threadIdx.x;  // pair index
    if (i >= VOCAB * 8) return;
    float2 x = reinterpret_cast<const float2*>(E)[i];
    __nv_bfloat162 h = __floats2bfloat162_rn(x.x, x.y);
    float lx = x.x - __bfloat162float(h.x);
    float ly = x.y - __bfloat162float(h.y);
    __nv_bfloat162 l = __floats2bfloat162_rn(lx, ly);
    g_ehi[i] = *reinterpret_cast<const unsigned*>(&h);
    g_elo[i] = *reinterpret_cast<const unsigned*>(&l);
}

// ---------------------------------------------------------------------------
// Kernel A: cooperative 16-lanes-per-row MLP pipeline (WIN from R6; only the
// final store changed: o is written as split bf16 instead of fp32).
// ---------------------------------------------------------------------------

#define S_M1 84
#define S_M2 116
#define S_M3 52

__device__ __forceinline__ void acc48(float acc[3], float v,
                                      const float* __restrict__ W, int S,
                                      int lane, int kbase) {
#pragma unroll
    for (int kk = 0; kk < 16; kk += 4) {
        float b0 = __shfl_sync(FULLM, v, kk + 0, 16);
        float b1 = __shfl_sync(FULLM, v, kk + 1, 16);
        float b2 = __shfl_sync(FULLM, v, kk + 2, 16);
        float b3 = __shfl_sync(FULLM, v, kk + 3, 16);
#pragma unroll
        for (int r = 0; r < 3; r++) {
            float4 w = *reinterpret_cast<const float4*>(
                &W[(lane + 16 * r) * S + kbase + kk]);
            acc[r] += w.x * b0 + w.y * b1 + w.z * b2 + w.w * b3;
        }
    }
}

__device__ __forceinline__ void acc16(float& acc, float v,
                                      const float* __restrict__ W, int S,
                                      int lane, int kbase) {
#pragma unroll
    for (int kk = 0; kk < 16; kk += 4) {
        float b0 = __shfl_sync(FULLM, v, kk + 0, 16);
        float b1 = __shfl_sync(FULLM, v, kk + 1, 16);
        float b2 = __shfl_sync(FULLM, v, kk + 2, 16);
        float b3 = __shfl_sync(FULLM, v, kk + 3, 16);
        float4 w = *reinterpret_cast<const float4*>(&W[lane * S + kbase + kk]);
        acc += w.x * b0 + w.y * b1 + w.z * b2 + w.w * b3;
    }
}

__device__ __forceinline__ void ln_silu3(float v[3],
                                         const float* __restrict__ g,
                                         const float* __restrict__ b,
                                         int lane) {
    float s = v[0] + v[1] + v[2];
    float q = v[0] * v[0] + v[1] * v[1] + v[2] * v[2];
#pragma unroll
    for (int off = 8; off >= 1; off >>= 1) {
        s += __shfl_xor_sync(FULLM, s, off, 16);
        q += __shfl_xor_sync(FULLM, q, off, 16);
    }
    float mu = s * (1.f / DIM1);
    float var = q * (1.f / DIM1) - mu * mu;
    float inv = rsqrtf(var + 1e-5f);
#pragma unroll
    for (int r = 0; r < 3; r++) {
        float t = (v[r] - mu) * inv * __ldg(&g[lane + 16 * r]) + __ldg(&b[lane + 16 * r]);
        v[r] = t / (1.f + expf(-t));
    }
}

__global__ void __launch_bounds__(512) rowmlp_kernel(
    const float* __restrict__ we, const float* __restrict__ ctx,
    const float* __restrict__ th,
    const float* __restrict__ WI1, const float* __restrict__ bI1,
    const float* __restrict__ WA1, const float* __restrict__ bA1,
    const float* __restrict__ WM1, const float* __restrict__ bM1,
    const float* __restrict__ WM2, const float* __restrict__ bM2,
    const float* __restrict__ WM3, const float* __restrict__ bM3,
    const float* __restrict__ lng, const float* __restrict__ lnb,
    const float* __restrict__ WO1, const float* __restrict__ bO1) {
    __shared__ __align__(16) float sWM1[DIM1 * S_M1];
    __shared__ __align__(16) float sWM2[DIM1 * S_M2];
    __shared__ __align__(16) float sWM3[DIM1 * S_M3];

    int tid = threadIdx.x;
    for (int i = tid; i < DIM1 * 80; i += 512) sWM1[(i / 80) * S_M1 + (i % 80)] = WM1[i];
    for (int i = tid; i < DIM1 * 112; i += 512) sWM2[(i / 112) * S_M2 + (i % 112)] = WM2[i];
    for (int i = tid; i < DIM1 * 48; i += 512) sWM3[(i / 48) * S_M3 + (i % 48)] = WM3[i];
    __syncthreads();

    int lane = tid & 15;
    int row = blockIdx.x * 32 + (tid >> 4);

    float x = we[(size_t)row * DIM + lane];
    float c = ctx[(size_t)row * DIM + lane];

    // layerI1: 16 -> 48
    float t0[3];
#pragma unroll
    for (int r = 0; r < 3; r++) t0[r] = __ldg(&bI1[lane + 16 * r]);
    {
#pragma unroll
        for (int kk = 0; kk < 16; kk += 4) {
            float b0 = __shfl_sync(FULLM, x, kk + 0, 16);
            float b1 = __shfl_sync(FULLM, x, kk + 1, 16);
            float b2 = __shfl_sync(FULLM, x, kk + 2, 16);
            float b3 = __shfl_sync(FULLM, x, kk + 3, 16);
#pragma unroll
            for (int r = 0; r < 3; r++) {
                float4 w = *reinterpret_cast<const float4*>(
                    &WI1[(lane + 16 * r) * 16 + kk]);
                t0[r] += w.x * b0 + w.y * b1 + w.z * b2 + w.w * b3;
            }
        }
    }

    // layerA1: 48 -> 16
    float op = __ldg(&bA1[lane]);
    acc16(op, t0[0], WA1, 48, lane, 0);
    acc16(op, t0[1], WA1, 48, lane, 16);
    acc16(op, t0[2], WA1, 48, lane, 32);

    // M1 over [t0(48), c(16), op(16)]
    float h[3];
#pragma unroll
    for (int r = 0; r < 3; r++) h[r] = __ldg(&bM1[lane + 16 * r]);
    acc48(h, t0[0], sWM1, S_M1, lane, 0);
    acc48(h, t0[1], sWM1, S_M1, lane, 16);
    acc48(h, t0[2], sWM1, S_M1, lane, 32);
    acc48(h, c, sWM1, S_M1, lane, 48);
    acc48(h, op, sWM1, S_M1, lane, 64);
    ln_silu3(h, lng, lnb, lane);

    // scores + top-3 (strict >, first occurrence == jax tie-break)
    float opAll[16];
#pragma unroll
    for (int k = 0; k < 16; k++) opAll[k] = __shfl_sync(FULLM, op, k, 16);

    const float* trow = th + (size_t)row * TTH * DIM;
    float s0 = 0.f;
    {
        const float4* tr = reinterpret_cast<const float4*>(trow + lane * DIM);
#pragma unroll
        for (int q = 0; q < 4; q++) {
            float4 a = tr[q];
            s0 += a.x * opAll[4 * q + 0] + a.y * opAll[4 * q + 1] +
                  a.z * opAll[4 * q + 2] + a.w * opAll[4 * q + 3];
        }
    }
    float s1 = -1e30f;
    if (lane < 4) {
        const float4* tr = reinterpret_cast<const float4*>(trow + (16 + lane) * DIM);
        float acc = 0.f;
#pragma unroll
        for (int q = 0; q < 4; q++) {
            float4 a = tr[q];
            acc += a.x * opAll[4 * q + 0] + a.y * opAll[4 * q + 1] +
                   a.z * opAll[4 * q + 2] + a.w * opAll[4 * q + 3];
        }
        s1 = acc;
    }
    float sc[TTH];
#pragma unroll
    for (int t = 0; t < 16; t++) sc[t] = __shfl_sync(FULLM, s0, t, 16);
#pragma unroll
    for (int t = 16; t < TTH; t++) sc[t] = __shfl_sync(FULLM, s1, t - 16, 16);

    int best[3];
#pragma unroll
    for (int s3 = 0; s3 < 3; s3++) {
        float bv = -1e30f;
        int bi = 0;
#pragma unroll
        for (int t = 0; t < TTH; t++) {
            if (sc[t] > bv) { bv = sc[t]; bi = t; }
        }
        best[s3] = bi;
#pragma unroll
        for (int t = 0; t < TTH; t++)
            if (t == bi) sc[t] = -1e30f;
    }

    float tp[3];
#pragma unroll
    for (int s3 = 0; s3 < 3; s3++) tp[s3] = __ldg(&trow[best[s3] * DIM + lane]);

    // M2 over [h(48), top_flat(48), c(16)]
    float h2[3];
#pragma unroll
    for (int r = 0; r < 3; r++) h2[r] = __ldg(&bM2[lane + 16 * r]);
    acc48(h2, h[0], sWM2, S_M2, lane, 0);
    acc48(h2, h[1], sWM2, S_M2, lane, 16);
    acc48(h2, h[2], sWM2, S_M2, lane, 32);
    acc48(h2, tp[0], sWM2, S_M2, lane, 48);
    acc48(h2, tp[1], sWM2, S_M2, lane, 64);
    acc48(h2, tp[2], sWM2, S_M2, lane, 80);
    acc48(h2, c, sWM2, S_M2, lane, 96);
    ln_silu3(h2, lng, lnb, lane);

    // M3: 48 -> 48
    float h3[3];
#pragma unroll
    for (int r = 0; r < 3; r++) h3[r] = __ldg(&bM3[lane + 16 * r]);
    acc48(h3, h2[0], sWM3, S_M3, lane, 0);
    acc48(h3, h2[1], sWM3, S_M3, lane, 16);
    acc48(h3, h2[2], sWM3, S_M3, lane, 32);
    ln_silu3(h3, lng, lnb, lane);

    // O1: 48 -> 16, store as split bf16 (hi + lo)
    float o = __ldg(&bO1[lane]);
    acc16(o, h3[0], WO1, 48, lane, 0);
    acc16(o, h3[1], WO1, 48, lane, 16);
    acc16(o, h3[2], WO1, 48, lane, 32);

    __nv_bfloat16 hi = __float2bfloat16(o);
    __nv_bfloat16 lo = __float2bfloat16(o - __bfloat162float(hi));
    reinterpret_cast<__nv_bfloat16*>(g_ohi)[row * 16 + lane] = hi;
    reinterpret_cast<__nv_bfloat16*>(g_olo)[row * 16 + lane] = lo;
}

// ---------------------------------------------------------------------------
// Kernel B: logits = o @ E^T via mma.sync.m16n8k16 bf16 with 2-term split:
//   D = o_hi*E_hi + o_hi*E_lo + o_lo*E_hi   (fp32 accum; lo*lo ~2^-18 dropped)
// Block: 128 thr / 4 warps; warp owns 16 rows x 64 cols (8 n8-tiles),
// B frags register-resident for 1024 rows (16 iters). Pure DRAM-write bound.
// ---------------------------------------------------------------------------
__device__ __forceinline__ void mma16816(float& d0, float& d1, float& d2, float& d3,
                                         unsigned a0, unsigned a1, unsigned a2,
                                         unsigned a3, unsigned b0, unsigned b1) {
    asm("mma.sync.aligned.m16n8k16.row.col.f32.bf16.bf16.f32 "
        "{%0,%1,%2,%3}, {%4,%5,%6,%7}, {%8,%9}, {%0,%1,%2,%3};"
        : "+f"(d0), "+f"(d1), "+f"(d2), "+f"(d3)
        : "r"(a0), "r"(a1), "r"(a2), "r"(a3), "r"(b0), "r"(b1));
}

__global__ void __launch_bounds__(128) logits_mma_kernel(float* __restrict__ out) {
    int w = threadIdx.x >> 5;
    int lane = threadIdx.x & 31;
    int g = lane >> 2;   // group id 0..7
    int c = lane & 3;    // thread-in-group 0..3
    int nb = blockIdx.x * 64;
    int rb = blockIdx.y * 1024;

    // B fragments for 8 n8-tiles (cols nb..nb+63), hi and lo.
    // b0: k-pair c (k=2c,2c+1), b1: k-pair c+4 (k=2c+8,2c+9), col = nb+8j+g.
    unsigned bh0[8], bh1[8], bl0[8], bl1[8];
#pragma unroll
    for (int j = 0; j < 8; j++) {
        int n = nb + 8 * j + g;
        bh0[j] = g_ehi[n * 8 + c];
        bh1[j] = g_ehi[n * 8 + c + 4];
        bl0[j] = g_elo[n * 8 + c];
        bl1[j] = g_elo[n * 8 + c + 4];
    }

#pragma unroll 2
    for (int it = 0; it < 16; it++) {
        int mrow = rb + it * 64 + w * 16;
        int row0 = mrow + g;
        int row1 = row0 + 8;
        // A fragments: a0 row0/kp c, a1 row1/kp c, a2 row0/kp c+4, a3 row1/kp c+4
        unsigned ah0 = g_ohi[row0 * 8 + c];
        unsigned ah1 = g_ohi[row1 * 8 + c];
        unsigned ah2 = g_ohi[row0 * 8 + c + 4];
        unsigned ah3 = g_ohi[row1 * 8 + c + 4];
        unsigned al0 = g_olo[row0 * 8 + c];
        unsigned al1 = g_olo[row1 * 8 + c];
        unsigned al2 = g_olo[row0 * 8 + c + 4];
        unsigned al3 = g_olo[row1 * 8 + c + 4];

        float* out0 = out + (size_t)row0 * VOCAB + nb + 2 * c;
        float* out1 = out + (size_t)row1 * VOCAB + nb + 2 * c;
#pragma unroll
        for (int j = 0; j < 8; j++) {
            float d0 = 0.f, d1 = 0.f, d2 = 0.f, d3 = 0.f;
            mma16816(d0, d1, d2, d3, ah0, ah1, ah2, ah3, bh0[j], bh1[j]);
            mma16816(d0, d1, d2, d3, ah0, ah1, ah2, ah3, bl0[j], bl1[j]);
            mma16816(d0, d1, d2, d3, al0, al1, al2, al3, bh0[j], bh1[j]);
            // d0,d1 -> (row0, cols 2c,2c+1) ; d2,d3 -> (row1, same cols)
            __stcs(reinterpret_cast<float2*>(out0 + 8 * j), make_float2(d0, d1));
            __stcs(reinterpret_cast<float2*>(out1 + 8 * j), make_float2(d2, d3));
        }
    }
}

// ---------------------------------------------------------------------------
extern "C" void kernel_launch(void* const* d_in, const int* in_sizes, int n_in,
                              void* d_out, int out_size) {
    const float* we  = (const float*)d_in[0];
    const float* ctx = (const float*)d_in[1];
    const float* th  = (const float*)d_in[2];
    const float* WI1 = (const float*)d_in[3];
    const float* bI1 = (const float*)d_in[4];
    const float* WA1 = (const float*)d_in[5];
    const float* bA1 = (const float*)d_in[6];
    const float* WM1 = (const float*)d_in[7];
    const float* bM1 = (const float*)d_in[8];
    const float* WM2 = (const float*)d_in[9];
    const float* bM2 = (const float*)d_in[10];
    const float* WM3 = (const float*)d_in[11];
    const float* bM3 = (const float*)d_in[12];
    const float* lng = (const float*)d_in[13];
    const float* lnb = (const float*)d_in[14];
    const float* WO1 = (const float*)d_in[15];
    const float* bO1 = (const float*)d_in[16];
    const float* E   = (const float*)d_in[17];
    float* out = (float*)d_out;

    convertE_kernel<<<(VOCAB * 8 + 255) / 256, 256>>>(E);
    rowmlp_kernel<<<256, 512>>>(we, ctx, th, WI1, bI1, WA1, bA1, WM1, bM1,
                                WM2, bM2, WM3, bM3, lng, lnb, WO1, bO1);
    // 64 cols/block x 500 ; 1024 rows/block x 8.
    logits_mma_kernel<<<dim3(VOCAB / 64, BATCH / 1024), 128>>>(out);
}